// round 5
// baseline (speedup 1.0000x reference)
#include <cuda_runtime.h>

#define FULLMASK 0xffffffffu
typedef unsigned long long ull;

__device__ __forceinline__ float ftanh(float x) {
    float y;
    asm("tanh.approx.f32 %0, %1;" : "=f"(y) : "f"(x));
    return y;
}
__device__ __forceinline__ float softplusf(float x) {
    return log1pf(__expf(x));
}
__device__ __forceinline__ ull fma2(ull a, ull b, ull c) {
    ull d;
    asm("fma.rn.f32x2 %0, %1, %2, %3;" : "=l"(d) : "l"(a), "l"(b), "l"(c));
    return d;
}
__device__ __forceinline__ ull pack2(float lo, float hi) {
    ull d;
    asm("mov.b64 %0, {%1, %2};" : "=l"(d) : "f"(lo), "f"(hi));
    return d;
}
__device__ __forceinline__ float2 unpack2(ull v) {
    float lo, hi;
    asm("mov.b64 {%0, %1}, %2;" : "=f"(lo), "=f"(hi) : "l"(v));
    return make_float2(lo, hi);
}

// One warp per batch element. Warp-synchronous UKF, f32x2-packed math.
__global__ void __launch_bounds__(32) ukf_kernel(
    const float* __restrict__ X0, const float* __restrict__ u, const float* __restrict__ yy,
    const float* __restrict__ W1, const float* __restrict__ b1,
    const float* __restrict__ W2, const float* __restrict__ b2,
    const float* __restrict__ Hm, const float* __restrict__ lq,
    const float* __restrict__ lr, const float* __restrict__ lp0,
    float* __restrict__ outX, float* __restrict__ outP,
    float* __restrict__ outQ, float* __restrict__ outR,
    int T)
{
    const float JIT = 1e-4f;
    const int b = blockIdx.x;
    const int lane = threadIdx.x;

    __shared__ __align__(16) float sP[64];         // P_new (8x8, stride 8)
    __shared__ __align__(16) float sPp[64];        // P_pred (8x8, stride 8)
    __shared__ __align__(16) float sL[64];         // chol(A) rows (8x8)
    __shared__ __align__(16) float sHid[17 * 36];  // tanh activations
    __shared__ __align__(16) float sDxT[8 * 20];   // dx transposed [col][s]
    __shared__ __align__(16) float sX[8];
    __shared__ __align__(16) float sXp[8];

    const int o  = lane & 7;    // state index / chol row
    const int q  = lane >> 3;   // sigma group / P row base
    const int m  = lane & 3;    // measurement index
    const int pn = lane >> 2;   // Pxy row
    const int si = pn & 3;      // Sy row index for this lane
    const int i1 = q, i2 = q + 4;
    const int g8 = lane & 8;    // dual-chol shuffle base
    const int b4 = lane & 28;   // 4-group base
    const int r4 = lane & 3;    // Sy chol row

    // ---- persistent per-lane weights (scalar + f32x2-packed) ----
    float w1c[10];
    #pragma unroll
    for (int d = 0; d < 10; ++d) w1c[d] = W1[d * 32 + lane];
    float b1v = b1[lane];
    ull w1p[4];
    #pragma unroll
    for (int jj = 0; jj < 4; ++jj) w1p[jj] = pack2(w1c[2 * jj], w1c[2 * jj + 1]);
    ull w2p[16];
    #pragma unroll
    for (int h = 0; h < 16; ++h)
        w2p[h] = pack2(W2[(2 * h) * 8 + o], W2[(2 * h + 1) * 8 + o]);
    float b2o = b2[o];
    float hmr[8];
    #pragma unroll
    for (int d = 0; d < 8; ++d) hmr[d] = Hm[m * 8 + d];
    ull hmp[4];
    #pragma unroll
    for (int jj = 0; jj < 4; ++jj) hmp[jj] = pack2(hmr[2 * jj], hmr[2 * jj + 1]);
    float hsr[8];
    #pragma unroll
    for (int d = 0; d < 8; ++d) hsr[d] = Hm[si * 8 + d];

    const float cD1 = (i1 == o) ? (softplusf(lq[i1]) + JIT) : 0.0f;
    const float cD2 = (i2 == o) ? (softplusf(lq[i2]) + JIT) : 0.0f;
    const float radd = (si == m) ? softplusf(lr[si]) : 0.0f;
    const float corrP = (softplusf(lq[pn]) + JIT) * Hm[m * 8 + pn];  // Pxy diag correction

    // ---- init: t=0 outputs, P0, identity Pp ----
    float xreg = X0[b * 8 + o];
    if (lane < 8) { sX[lane] = xreg; outX[(long)b * T * 8 + lane] = xreg; }
    #pragma unroll
    for (int rep = 0; rep < 2; ++rep) {
        int idx = lane + 32 * rep;
        int ii = idx >> 3, jj = idx & 7;
        float pv = (ii == jj) ? softplusf(lp0[ii]) : 0.0f;
        sP[idx] = pv;
        sPp[idx] = (ii == jj) ? 1.0f : 0.0f;
        outP[(long)b * T * 64 + idx] = pv;
    }
    if (lane == 0) { outQ[(long)b * T] = 0.0f; outR[(long)b * T] = 0.0f; }
    __syncwarp();

    for (int t = 1; t < T; ++t) {
        const float2 uv = *reinterpret_cast<const float2*>(&u[((long)b * T + (t - 1)) * 2]);

        // ==== dual shuffle-Cholesky: bit3=0 -> A=8P+JIT*I ; bit3=1 -> Pp_prev ====
        float a[8];
        {
            const float4* srcp = reinterpret_cast<const float4*>(g8 ? &sPp[o * 8] : &sP[o * 8]);
            float4 r0 = srcp[0], r1 = srcp[1];
            a[0] = r0.x; a[1] = r0.y; a[2] = r0.z; a[3] = r0.w;
            a[4] = r1.x; a[5] = r1.y; a[6] = r1.z; a[7] = r1.w;
            if (!g8) {
                #pragma unroll
                for (int c = 0; c < 8; ++c)
                    a[c] = 8.0f * a[c] + ((c == o) ? JIT : 0.0f);
            }
        }
        float mydiag8 = 1.0f;
        #pragma unroll
        for (int k = 0; k < 8; ++k) {
            float akk = __shfl_sync(FULLMASK, a[k], g8 + k);
            float inv = rsqrtf(akk);
            float lk = a[k] * inv;
            if (o == k) { a[k] = akk * inv; mydiag8 = a[k]; }
            else if (o > k) a[k] = lk;
            #pragma unroll
            for (int jj = k + 1; jj < 8; ++jj) {
                float lj = __shfl_sync(FULLMASK, a[k], g8 + jj);
                if (o >= jj) a[jj] -= a[k] * lj;
            }
        }
        // deferred q_e of previous step (lanes 8-15 hold L(Pp_prev))
        {
            float lg = __logf(mydiag8);
            lg += __shfl_xor_sync(FULLMASK, lg, 1);
            lg += __shfl_xor_sync(FULLMASK, lg, 2);
            lg += __shfl_xor_sync(FULLMASK, lg, 4);
            if (lane == 8 && t >= 2) outQ[(long)b * T + (t - 1)] = lg;
        }
        // lanes 0-7 publish L(A) rows (junk above diag is masked by consumers)
        if (lane < 8) {
            float4* dst = reinterpret_cast<float4*>(&sL[o * 8]);
            dst[0] = make_float4(a[0], a[1], a[2], a[3]);
            dst[1] = make_float4(a[4], a[5], a[6], a[7]);
        }
        __syncwarp();

        // ==== G[i] = sum_{d>=i} L[d][i]*w1c[d] via row broadcasts ====
        float G[8];
        {
            const float4* lr4 = reinterpret_cast<const float4*>(sL);
            float4 r = lr4[0];
            G[0] = w1c[0] * r.x;
            r = lr4[2];
            G[0] += w1c[1] * r.x; G[1] = w1c[1] * r.y;
            r = lr4[4];
            G[0] += w1c[2] * r.x; G[1] += w1c[2] * r.y; G[2] = w1c[2] * r.z;
            r = lr4[6];
            G[0] += w1c[3] * r.x; G[1] += w1c[3] * r.y; G[2] += w1c[3] * r.z; G[3] = w1c[3] * r.w;
            float4 r0 = lr4[8], r1 = lr4[9];
            G[0] += w1c[4] * r0.x; G[1] += w1c[4] * r0.y; G[2] += w1c[4] * r0.z; G[3] += w1c[4] * r0.w;
            G[4] = w1c[4] * r1.x;
            r0 = lr4[10]; r1 = lr4[11];
            G[0] += w1c[5] * r0.x; G[1] += w1c[5] * r0.y; G[2] += w1c[5] * r0.z; G[3] += w1c[5] * r0.w;
            G[4] += w1c[5] * r1.x; G[5] = w1c[5] * r1.y;
            r0 = lr4[12]; r1 = lr4[13];
            G[0] += w1c[6] * r0.x; G[1] += w1c[6] * r0.y; G[2] += w1c[6] * r0.z; G[3] += w1c[6] * r0.w;
            G[4] += w1c[6] * r1.x; G[5] += w1c[6] * r1.y; G[6] = w1c[6] * r1.z;
            r0 = lr4[14]; r1 = lr4[15];
            G[0] += w1c[7] * r0.x; G[1] += w1c[7] * r0.y; G[2] += w1c[7] * r0.z; G[3] += w1c[7] * r0.w;
            G[4] += w1c[7] * r1.x; G[5] += w1c[7] * r1.y; G[6] += w1c[7] * r1.z; G[7] = w1c[7] * r1.w;
        }
        // own L row (zeros above diagonal)
        float Lrow[8];
        {
            const float4* lr4 = reinterpret_cast<const float4*>(&sL[o * 8]);
            float4 r0 = lr4[0], r1 = lr4[1];
            Lrow[0] = r0.x;
            Lrow[1] = (o >= 1) ? r0.y : 0.0f;
            Lrow[2] = (o >= 2) ? r0.z : 0.0f;
            Lrow[3] = (o >= 3) ? r0.w : 0.0f;
            Lrow[4] = (o >= 4) ? r1.x : 0.0f;
            Lrow[5] = (o >= 5) ? r1.y : 0.0f;
            Lrow[6] = (o >= 6) ? r1.z : 0.0f;
            Lrow[7] = (o >= 7) ? r1.w : 0.0f;
        }
        // hidden-layer base: bx = b1 + u*W1u + x*W1x (packed dot)
        float bx = b1v + uv.x * w1c[8] + uv.y * w1c[9];
        {
            const ulonglong2* xp2 = reinterpret_cast<const ulonglong2*>(sX);
            ulonglong2 xv = xp2[0];
            ull acc = fma2(xv.x, w1p[0], 0ULL);
            acc = fma2(xv.y, w1p[1], acc);
            xv = xp2[1];
            acc = fma2(xv.x, w1p[2], acc);
            acc = fma2(xv.y, w1p[3], acc);
            float2 f = unpack2(acc);
            bx += f.x + f.y;
        }

        sHid[0 * 36 + lane] = ftanh(bx);
        #pragma unroll
        for (int i = 0; i < 8; ++i) {
            sHid[(1 + i) * 36 + lane] = ftanh(bx + G[i]);
            sHid[(9 + i) * 36 + lane] = ftanh(bx - G[i]);
        }
        __syncwarp();

        // ==== output layer (FFMA2) + x_pred + dx (stored transposed) ====
        float pf[5];
        float xsum = 0.0f;
        #pragma unroll
        for (int g = 0; g < 5; ++g) {
            int s = 4 * g + q;
            bool valid = (s < 17);
            int ss = valid ? s : 0;
            const ulonglong2* hp = reinterpret_cast<const ulonglong2*>(&sHid[ss * 36]);
            ull e2 = 0ULL;
            #pragma unroll
            for (int hh = 0; hh < 8; ++hh) {
                ulonglong2 hv = hp[hh];
                e2 = fma2(hv.x, w2p[2 * hh], e2);
                e2 = fma2(hv.y, w2p[2 * hh + 1], e2);
            }
            float2 ef = unpack2(e2);
            float e = b2o + ef.x + ef.y;
            float delta = 0.0f;
            if (ss >= 1 && ss <= 8) delta = Lrow[ss - 1];
            else if (ss >= 9)       delta = -Lrow[ss - 9];
            float p = xreg + delta + e;
            pf[g] = p;
            if (valid && s >= 1) xsum += p;      // Wm[0] = 0
        }
        xsum += __shfl_xor_sync(FULLMASK, xsum, 8);
        xsum += __shfl_xor_sync(FULLMASK, xsum, 16);
        const float xpred = xsum * 0.0625f;
        if (lane < 8) sXp[o] = xpred;
        #pragma unroll
        for (int g = 0; g < 5; ++g) {
            int s = 4 * g + q;
            if (s < 17) sDxT[o * 20 + s] = pf[g] - xpred;
        }
        __syncwarp();

        // ==== Cx (16x scaled) via packed dots: a1=16*Cx[i1][o], a2=16*Cx[i2][o] ====
        float a1, a2;
        {
            const ulonglong2* cq = reinterpret_cast<const ulonglong2*>(&sDxT[i1 * 20]);
            const ulonglong2* c2 = reinterpret_cast<const ulonglong2*>(&sDxT[i2 * 20]);
            const ulonglong2* co = reinterpret_cast<const ulonglong2*>(&sDxT[o * 20]);
            ull A1 = 0ULL, A2 = 0ULL;
            #pragma unroll
            for (int c = 0; c < 4; ++c) {
                ulonglong2 vq = cq[c], v2 = c2[c], vo = co[c];
                A1 = fma2(vq.x, vo.x, A1);
                A1 = fma2(vq.y, vo.y, A1);
                A2 = fma2(v2.x, vo.x, A2);
                A2 = fma2(v2.y, vo.y, A2);
            }
            float2 f1 = unpack2(A1), f2v = unpack2(A2);
            float o16v = sDxT[o * 20 + 16], q16 = sDxT[i1 * 20 + 16], t16 = sDxT[i2 * 20 + 16];
            float dx0o = sDxT[o * 20], dx0q = sDxT[i1 * 20], dx0t = sDxT[i2 * 20];
            // uniform 17-term sum + (Wc0-1)=31 extra on s=0
            a1 = f1.x + f1.y + q16 * o16v + 31.0f * dx0q * dx0o;
            a2 = f2v.x + f2v.y + t16 * o16v + 31.0f * dx0t * dx0o;
        }
        const float ppa = a1 * 0.0625f + cD1;   // P_pred[i1][o]
        const float ppb = a2 * 0.0625f + cD2;   // P_pred[i2][o]
        sPp[i1 * 8 + o] = ppa;
        sPp[i2 * 8 + o] = ppb;
        __syncwarp();

        // ==== Pxy[pn][m] = (P_pred - diag(Q+JIT)) row_pn . Hm_row_m ====
        float pxy;
        {
            const ulonglong2* pr = reinterpret_cast<const ulonglong2*>(&sPp[pn * 8]);
            ulonglong2 pv0 = pr[0];
            ull acc = fma2(pv0.x, hmp[0], 0ULL);
            acc = fma2(pv0.y, hmp[1], acc);
            ulonglong2 pv1 = pr[1];
            acc = fma2(pv1.x, hmp[2], acc);
            acc = fma2(pv1.y, hmp[3], acc);
            float2 f = unpack2(acc);
            pxy = f.x + f.y - corrP;
        }
        // ==== Sy[si][m] = Hm row_si . Pxy col_m + R ====
        float syv = radd;
        #pragma unroll
        for (int d = 0; d < 8; ++d) {
            float pv = __shfl_sync(FULLMASK, pxy, d * 4 + m);
            syv += hsr[d] * pv;
        }

        // ==== Sy 4x4 shuffle-Cholesky (4-lane groups) ====
        float s4[4];
        #pragma unroll
        for (int c = 0; c < 4; ++c)
            s4[c] = __shfl_sync(FULLMASK, syv, r4 * 4 + c);
        float myinv4 = 1.0f, mydiag4 = 1.0f;
        #pragma unroll
        for (int k = 0; k < 4; ++k) {
            float akk = __shfl_sync(FULLMASK, s4[k], b4 + k);
            float inv = rsqrtf(akk);
            float lk = s4[k] * inv;
            if (r4 == k) { s4[k] = akk * inv; myinv4 = inv; mydiag4 = s4[k]; }
            else if (r4 > k) s4[k] = lk;
            #pragma unroll
            for (int jj = k + 1; jj < 4; ++jj) {
                float lj = __shfl_sync(FULLMASK, s4[k], b4 + jj);
                if (r4 >= jj) s4[jj] -= s4[k] * lj;
            }
        }
        {
            float lg = __logf(mydiag4);
            lg += __shfl_xor_sync(FULLMASK, lg, 1);
            lg += __shfl_xor_sync(FULLMASK, lg, 2);
            if (lane == 0) outR[(long)b * T + t] = lg;
        }
        const float d0 = __shfl_sync(FULLMASK, myinv4, b4 + 0);
        const float d1 = __shfl_sync(FULLMASK, myinv4, b4 + 1);
        const float d2 = __shfl_sync(FULLMASK, myinv4, b4 + 2);
        const float d3 = __shfl_sync(FULLMASK, myinv4, b4 + 3);
        const float Ld0 = __shfl_sync(FULLMASK, mydiag4, b4 + 0);
        const float Ld1 = __shfl_sync(FULLMASK, mydiag4, b4 + 1);
        const float Ld2 = __shfl_sync(FULLMASK, mydiag4, b4 + 2);
        const float Ld3 = __shfl_sync(FULLMASK, mydiag4, b4 + 3);
        const float L10 = __shfl_sync(FULLMASK, s4[0], b4 + 1);
        const float L20 = __shfl_sync(FULLMASK, s4[0], b4 + 2);
        const float L30 = __shfl_sync(FULLMASK, s4[0], b4 + 3);
        const float L21 = __shfl_sync(FULLMASK, s4[1], b4 + 2);
        const float L31 = __shfl_sync(FULLMASK, s4[1], b4 + 3);
        const float L32 = __shfl_sync(FULLMASK, s4[2], b4 + 3);

        // ==== K row o via two triangular solves ====
        float w0 = __shfl_sync(FULLMASK, pxy, o * 4 + 0);
        float w1 = __shfl_sync(FULLMASK, pxy, o * 4 + 1);
        float w2 = __shfl_sync(FULLMASK, pxy, o * 4 + 2);
        float w3 = __shfl_sync(FULLMASK, pxy, o * 4 + 3);
        w0 = w0 * d0;
        w1 = (w1 - L10 * w0) * d1;
        w2 = (w2 - L20 * w0 - L21 * w1) * d2;
        w3 = (w3 - L30 * w0 - L31 * w1 - L32 * w2) * d3;
        float z3 = w3 * d3;
        float z2 = (w2 - L32 * z3) * d2;
        float z1 = (w1 - L21 * z2 - L31 * z3) * d1;
        float z0 = (w0 - L10 * z1 - L20 * z2 - L30 * z3) * d0;

        // ==== innovation & state update ====
        float inno;
        {
            const ulonglong2* xpp = reinterpret_cast<const ulonglong2*>(sXp);
            ulonglong2 xv = xpp[0];
            ull acc = fma2(xv.x, hmp[0], 0ULL);
            acc = fma2(xv.y, hmp[1], acc);
            xv = xpp[1];
            acc = fma2(xv.x, hmp[2], acc);
            acc = fma2(xv.y, hmp[3], acc);
            float2 f = unpack2(acc);
            inno = yy[((long)b * T + t) * 4 + m] - (f.x + f.y);
        }
        const float in0 = __shfl_sync(FULLMASK, inno, b4 + 0);
        const float in1 = __shfl_sync(FULLMASK, inno, b4 + 1);
        const float in2 = __shfl_sync(FULLMASK, inno, b4 + 2);
        const float in3 = __shfl_sync(FULLMASK, inno, b4 + 3);
        float xn = xpred + z0 * in0 + z1 * in1 + z2 * in2 + z3 * in3;
        xreg = xn;
        if (lane < 8) { sX[o] = xn; outX[((long)b * T + t) * 8 + o] = xn; }

        // ==== U = K * L(Sy), P_new = Ppred - U U^T + JIT*I (bitwise symmetric) ====
        float U0 = z0 * Ld0 + z1 * L10 + z2 * L20 + z3 * L30;
        float U1 = z1 * Ld1 + z2 * L21 + z3 * L31;
        float U2 = z2 * Ld2 + z3 * L32;
        float U3 = z3 * Ld3;
        float Ua0 = __shfl_sync(FULLMASK, U0, q);
        float Ua1 = __shfl_sync(FULLMASK, U1, q);
        float Ua2 = __shfl_sync(FULLMASK, U2, q);
        float Ua3 = __shfl_sync(FULLMASK, U3, q);
        float Ub0 = __shfl_sync(FULLMASK, U0, q + 4);
        float Ub1 = __shfl_sync(FULLMASK, U1, q + 4);
        float Ub2 = __shfl_sync(FULLMASK, U2, q + 4);
        float Ub3 = __shfl_sync(FULLMASK, U3, q + 4);
        float p1 = ppa - (Ua0 * U0 + Ua1 * U1 + Ua2 * U2 + Ua3 * U3) + ((i1 == o) ? JIT : 0.0f);
        float p2 = ppb - (Ub0 * U0 + Ub1 * U1 + Ub2 * U2 + Ub3 * U3) + ((i2 == o) ? JIT : 0.0f);
        sP[i1 * 8 + o] = p1;
        sP[i2 * 8 + o] = p2;
        long bp = ((long)b * T + t) * 64;
        outP[bp + i1 * 8 + o] = p1;
        outP[bp + i2 * 8 + o] = p2;
        __syncwarp();
    }

    // ==== epilogue: q_e[T-1] from final P_pred ====
    {
        float a[8];
        #pragma unroll
        for (int c = 0; c < 8; ++c) a[c] = sPp[o * 8 + c];
        float md = 1.0f;
        #pragma unroll
        for (int k = 0; k < 8; ++k) {
            float akk = __shfl_sync(FULLMASK, a[k], k);
            float inv = rsqrtf(akk);
            float lk = a[k] * inv;
            if (o == k) { a[k] = akk * inv; md = a[k]; }
            else if (o > k) a[k] = lk;
            #pragma unroll
            for (int jj = k + 1; jj < 8; ++jj) {
                float lj = __shfl_sync(FULLMASK, a[k], jj);
                if (o >= jj) a[jj] -= a[k] * lj;
            }
        }
        float lg = __logf(md);
        lg += __shfl_xor_sync(FULLMASK, lg, 1);
        lg += __shfl_xor_sync(FULLMASK, lg, 2);
        lg += __shfl_xor_sync(FULLMASK, lg, 4);
        if (lane == 0) outQ[(long)b * T + (T - 1)] = lg;
    }
}

extern "C" void kernel_launch(void* const* d_in, const int* in_sizes, int n_in,
                              void* d_out, int out_size) {
    const float* X0  = (const float*)d_in[0];
    const float* u   = (const float*)d_in[1];
    const float* yv  = (const float*)d_in[2];
    const float* W1  = (const float*)d_in[3];
    const float* b1  = (const float*)d_in[4];
    const float* W2  = (const float*)d_in[5];
    const float* b2  = (const float*)d_in[6];
    const float* Hm  = (const float*)d_in[7];
    const float* lq  = (const float*)d_in[8];
    const float* lr  = (const float*)d_in[9];
    const float* lp0 = (const float*)d_in[10];

    const int B = in_sizes[0] / 8;                 // 1024
    const int T = in_sizes[1] / (B * 2);           // 256

    float* out  = (float*)d_out;
    float* outX = out;
    float* outP = out + (long)B * T * 8;
    float* outQ = out + (long)B * T * (8 + 64);
    float* outR = outQ + (long)B * T;

    ukf_kernel<<<B, 32>>>(X0, u, yv, W1, b1, W2, b2, Hm, lq, lr, lp0,
                          outX, outP, outQ, outR, T);
}

// round 6
// speedup vs baseline: 1.2179x; 1.2179x over previous
#include <cuda_runtime.h>

#define FULLMASK 0xffffffffu

__device__ __forceinline__ float ftanh(float x) {
    float y;
    asm("tanh.approx.f32 %0, %1;" : "=f"(y) : "f"(x));
    return y;
}
__device__ __forceinline__ float softplusf(float x) {
    return log1pf(__expf(x));
}

// One warp per batch element. Shuffle-heavy warp-synchronous UKF.
__global__ void __launch_bounds__(32) ukf_kernel(
    const float* __restrict__ X0, const float* __restrict__ u, const float* __restrict__ yy,
    const float* __restrict__ W1, const float* __restrict__ b1,
    const float* __restrict__ W2, const float* __restrict__ b2,
    const float* __restrict__ Hm, const float* __restrict__ lq,
    const float* __restrict__ lr, const float* __restrict__ lp0,
    float* __restrict__ outX, float* __restrict__ outP,
    float* __restrict__ outQ, float* __restrict__ outR,
    int T)
{
    const float JIT = 1e-4f;
    const int b = blockIdx.x;
    const int lane = threadIdx.x;

    __shared__ float sP[72];                       // P_new handoff (8x9)
    __shared__ float sPp[72];                      // P_pred handoff (8x9)
    __shared__ __align__(16) float sHid[17 * 36];  // tanh activations
    __shared__ __align__(16) float sDxT[8 * 20];   // dx TRANSPOSED: [col][s], 80B rows

    const int o  = lane & 7;    // state index / chol row
    const int q  = lane >> 3;   // sigma group / P row base
    const int m  = lane & 3;    // measurement index
    const int pn = lane >> 2;   // Pxy row
    const int si = pn & 3;      // Sy row index for this lane
    const int i1 = q, i2 = q + 4;
    const int g8 = lane & 8;    // dual-chol shuffle base
    const int b4 = lane & 28;   // 4-group base
    const int r4 = lane & 3;    // Sy chol row

    // ---- persistent per-lane weights in registers ----
    float w1c[10];
    #pragma unroll
    for (int d = 0; d < 10; ++d) w1c[d] = W1[d * 32 + lane];
    float b1v = b1[lane];
    float w2c[32];
    #pragma unroll
    for (int h = 0; h < 32; ++h) w2c[h] = W2[h * 8 + o];
    float b2o = b2[o];
    float hmr[8];                 // Hm row m (this lane's measurement idx)
    #pragma unroll
    for (int d = 0; d < 8; ++d) hmr[d] = Hm[m * 8 + d];
    float hsr[8];                 // Hm row si (for Sy assembly)
    #pragma unroll
    for (int d = 0; d < 8; ++d) hsr[d] = Hm[si * 8 + d];

    const float cD1 = (i1 == o) ? (softplusf(lq[i1]) + JIT) : 0.0f;
    const float cD2 = (i2 == o) ? (softplusf(lq[i2]) + JIT) : 0.0f;
    const float radd = (si == m) ? softplusf(lr[si]) : 0.0f;

    // ---- init: t=0 outputs, P0, identity Pp (benign for t=1 dual-chol) ----
    float xreg = X0[b * 8 + o];
    if (lane < 8) outX[(long)b * T * 8 + lane] = xreg;
    #pragma unroll
    for (int rep = 0; rep < 2; ++rep) {
        int idx = lane + 32 * rep;
        int ii = idx >> 3, jj = idx & 7;
        float pv = (ii == jj) ? softplusf(lp0[ii]) : 0.0f;
        sP[ii * 9 + jj] = pv;
        sPp[ii * 9 + jj] = (ii == jj) ? 1.0f : 0.0f;
        outP[(long)b * T * 64 + idx] = pv;
    }
    if (lane == 0) { outQ[(long)b * T] = 0.0f; outR[(long)b * T] = 0.0f; }
    __syncwarp();

    for (int t = 1; t < T; ++t) {
        const float u0 = u[((long)b * T + (t - 1)) * 2 + 0];
        const float u1 = u[((long)b * T + (t - 1)) * 2 + 1];

        // ==== dual shuffle-Cholesky: bit3=0 lanes -> A=8P+JIT*I ; bit3=1 -> Pp_prev ====
        float a[8];
        #pragma unroll
        for (int c = 0; c < 8; ++c)
            a[c] = g8 ? sPp[o * 9 + c]
                      : (8.0f * sP[o * 9 + c] + ((o == c) ? JIT : 0.0f));
        float mydiag8 = 1.0f;
        #pragma unroll
        for (int k = 0; k < 8; ++k) {
            float akk = __shfl_sync(FULLMASK, a[k], g8 + k);
            float inv = rsqrtf(akk);
            float lk = a[k] * inv;
            if (o == k) { a[k] = akk * inv; mydiag8 = a[k]; }
            else if (o > k) a[k] = lk;
            #pragma unroll
            for (int jj = k + 1; jj < 8; ++jj) {
                float lj = __shfl_sync(FULLMASK, a[k], g8 + jj);
                if (o >= jj) a[jj] -= a[k] * lj;
            }
        }
        // deferred q_e of previous step (lanes 8-15 hold L(Pp_prev))
        {
            float lg = __logf(mydiag8);
            lg += __shfl_xor_sync(FULLMASK, lg, 1);
            lg += __shfl_xor_sync(FULLMASK, lg, 2);
            lg += __shfl_xor_sync(FULLMASK, lg, 4);
            if (lane == 8 && t >= 2) outQ[(long)b * T + (t - 1)] = lg;
        }
        // L(A) row for own state o (src lanes 0..7 hold L(A) rows)
        float Lrow[8];
        #pragma unroll
        for (int i = 0; i < 8; ++i) {
            float lv = __shfl_sync(FULLMASK, a[i], o);
            Lrow[i] = (i <= o) ? lv : 0.0f;
        }
        // G[i] = sum_{d>=i} L[d][i] * w1c[d]
        float G[8];
        #pragma unroll
        for (int i = 0; i < 8; ++i) {
            float g = 0.0f;
            #pragma unroll
            for (int d = i; d < 8; ++d)
                g += __shfl_sync(FULLMASK, a[i], d) * w1c[d];
            G[i] = g;
        }
        // hidden-layer base from register state x
        float bx = b1v + u0 * w1c[8] + u1 * w1c[9];
        #pragma unroll
        for (int d = 0; d < 8; ++d)
            bx += __shfl_sync(FULLMASK, xreg, d) * w1c[d];

        sHid[0 * 36 + lane] = ftanh(bx);
        #pragma unroll
        for (int i = 0; i < 8; ++i) {
            sHid[(1 + i) * 36 + lane] = ftanh(bx + G[i]);
            sHid[(9 + i) * 36 + lane] = ftanh(bx - G[i]);
        }
        __syncwarp();

        // ==== output layer + x_pred + dx (stored transposed) ====
        float pf[5];
        float xsum = 0.0f;
        #pragma unroll
        for (int g = 0; g < 5; ++g) {
            int s = 4 * g + q;
            bool valid = (s < 17);
            int ss = valid ? s : 0;
            const float4* hp = reinterpret_cast<const float4*>(&sHid[ss * 36]);
            float e = b2o;
            #pragma unroll
            for (int hh = 0; hh < 8; ++hh) {
                float4 hv = hp[hh];
                e += hv.x * w2c[4 * hh] + hv.y * w2c[4 * hh + 1]
                   + hv.z * w2c[4 * hh + 2] + hv.w * w2c[4 * hh + 3];
            }
            float delta = 0.0f;
            if (ss >= 1 && ss <= 8) delta = Lrow[ss - 1];
            else if (ss >= 9)       delta = -Lrow[ss - 9];
            float p = xreg + delta + e;
            pf[g] = p;
            if (valid && s >= 1) xsum += p;      // Wm[0] = 0
        }
        xsum += __shfl_xor_sync(FULLMASK, xsum, 8);
        xsum += __shfl_xor_sync(FULLMASK, xsum, 16);
        const float xpred = xsum * 0.0625f;
        #pragma unroll
        for (int g = 0; g < 5; ++g) {
            int s = 4 * g + q;
            if (s < 17) sDxT[o * 20 + s] = pf[g] - xpred;   // transposed, conflict-free
        }
        __syncwarp();

        // ==== Cx raw (16x scaled): a1 = 16*Cx[i1][o], a2 = 16*Cx[i2][o] ====
        float a1, a2;
        {
            const float4* cq = reinterpret_cast<const float4*>(&sDxT[i1 * 20]);
            const float4* c2 = reinterpret_cast<const float4*>(&sDxT[i2 * 20]);
            const float4* co = reinterpret_cast<const float4*>(&sDxT[o * 20]);
            float4 xq = cq[0], x2 = c2[0], xo = co[0];
            // s=0 carries Wc0 = 2 = 32/16
            a1 = 32.0f * xq.x * xo.x + xq.y * xo.y + xq.z * xo.z + xq.w * xo.w;
            a2 = 32.0f * x2.x * xo.x + x2.y * xo.y + x2.z * xo.z + x2.w * xo.w;
            #pragma unroll
            for (int c = 1; c < 4; ++c) {
                xq = cq[c]; x2 = c2[c]; xo = co[c];
                a1 += xq.x * xo.x + xq.y * xo.y + xq.z * xo.z + xq.w * xo.w;
                a2 += x2.x * xo.x + x2.y * xo.y + x2.z * xo.z + x2.w * xo.w;
            }
            float q16 = sDxT[i1 * 20 + 16], t16 = sDxT[i2 * 20 + 16], o16 = sDxT[o * 20 + 16];
            a1 += q16 * o16;
            a2 += t16 * o16;
        }
        const float ppa = a1 * 0.0625f + cD1;   // P_pred[i1][o]
        const float ppb = a2 * 0.0625f + cD2;   // P_pred[i2][o]
        sPp[i1 * 9 + o] = ppa;   // handoff for next-iter deferred chol
        sPp[i2 * 9 + o] = ppb;

        // ==== Pxy[pn][m] = (Cx Hm^T)[pn][m] via shuffled Cx entries ====
        float pxy = 0.0f;
        {
            const int sb8 = (pn & 3) * 8;
            #pragma unroll
            for (int d = 0; d < 8; ++d) {
                float v1 = __shfl_sync(FULLMASK, a1, sb8 + d);
                float v2 = __shfl_sync(FULLMASK, a2, sb8 + d);
                float cv = (pn < 4) ? v1 : v2;
                pxy += cv * hmr[d];
            }
            pxy *= 0.0625f;
        }
        // ==== Sy[si][m] = (Hm Pxy)[si][m] + R ====
        float syv = radd;
        #pragma unroll
        for (int d = 0; d < 8; ++d) {
            float pv = __shfl_sync(FULLMASK, pxy, d * 4 + m);
            syv += hsr[d] * pv;
        }

        // ==== Sy 4x4 shuffle-Cholesky (4-lane groups) ====
        float s4[4];
        #pragma unroll
        for (int c = 0; c < 4; ++c)
            s4[c] = __shfl_sync(FULLMASK, syv, r4 * 4 + c);
        float myinv4 = 1.0f, mydiag4 = 1.0f;
        #pragma unroll
        for (int k = 0; k < 4; ++k) {
            float akk = __shfl_sync(FULLMASK, s4[k], b4 + k);
            float inv = rsqrtf(akk);
            float lk = s4[k] * inv;
            if (r4 == k) { s4[k] = akk * inv; myinv4 = inv; mydiag4 = s4[k]; }
            else if (r4 > k) s4[k] = lk;
            #pragma unroll
            for (int jj = k + 1; jj < 4; ++jj) {
                float lj = __shfl_sync(FULLMASK, s4[k], b4 + jj);
                if (r4 >= jj) s4[jj] -= s4[k] * lj;
            }
        }
        {
            float lg = __logf(mydiag4);
            lg += __shfl_xor_sync(FULLMASK, lg, 1);
            lg += __shfl_xor_sync(FULLMASK, lg, 2);
            if (lane == 0) outR[(long)b * T + t] = lg;
        }
        // broadcast L(Sy) pieces
        const float d0 = __shfl_sync(FULLMASK, myinv4, b4 + 0);
        const float d1 = __shfl_sync(FULLMASK, myinv4, b4 + 1);
        const float d2 = __shfl_sync(FULLMASK, myinv4, b4 + 2);
        const float d3 = __shfl_sync(FULLMASK, myinv4, b4 + 3);
        const float Ld0 = __shfl_sync(FULLMASK, mydiag4, b4 + 0);
        const float Ld1 = __shfl_sync(FULLMASK, mydiag4, b4 + 1);
        const float Ld2 = __shfl_sync(FULLMASK, mydiag4, b4 + 2);
        const float Ld3 = __shfl_sync(FULLMASK, mydiag4, b4 + 3);
        const float L10 = __shfl_sync(FULLMASK, s4[0], b4 + 1);
        const float L20 = __shfl_sync(FULLMASK, s4[0], b4 + 2);
        const float L30 = __shfl_sync(FULLMASK, s4[0], b4 + 3);
        const float L21 = __shfl_sync(FULLMASK, s4[1], b4 + 2);
        const float L31 = __shfl_sync(FULLMASK, s4[1], b4 + 3);
        const float L32 = __shfl_sync(FULLMASK, s4[2], b4 + 3);

        // ==== K row o via two triangular solves (Pxy row via shuffle) ====
        float w0 = __shfl_sync(FULLMASK, pxy, o * 4 + 0);
        float w1 = __shfl_sync(FULLMASK, pxy, o * 4 + 1);
        float w2 = __shfl_sync(FULLMASK, pxy, o * 4 + 2);
        float w3 = __shfl_sync(FULLMASK, pxy, o * 4 + 3);
        w0 = w0 * d0;
        w1 = (w1 - L10 * w0) * d1;
        w2 = (w2 - L20 * w0 - L21 * w1) * d2;
        w3 = (w3 - L30 * w0 - L31 * w1 - L32 * w2) * d3;
        float z3 = w3 * d3;
        float z2 = (w2 - L32 * z3) * d2;
        float z1 = (w1 - L21 * z2 - L31 * z3) * d1;
        float z0 = (w0 - L10 * z1 - L20 * z2 - L30 * z3) * d0;

        // ==== innovation & state update ====
        float ypm = 0.0f;
        #pragma unroll
        for (int d = 0; d < 8; ++d)
            ypm += hmr[d] * __shfl_sync(FULLMASK, xpred, d);
        float inno = yy[((long)b * T + t) * 4 + m] - ypm;
        const float in0 = __shfl_sync(FULLMASK, inno, b4 + 0);
        const float in1 = __shfl_sync(FULLMASK, inno, b4 + 1);
        const float in2 = __shfl_sync(FULLMASK, inno, b4 + 2);
        const float in3 = __shfl_sync(FULLMASK, inno, b4 + 3);
        float xn = xpred + z0 * in0 + z1 * in1 + z2 * in2 + z3 * in3;
        xreg = xn;
        if (lane < 8) outX[((long)b * T + t) * 8 + o] = xn;

        // ==== U = K * L(Sy), P_new = Ppred - U U^T + JIT*I (bitwise symmetric) ====
        float U0 = z0 * Ld0 + z1 * L10 + z2 * L20 + z3 * L30;
        float U1 = z1 * Ld1 + z2 * L21 + z3 * L31;
        float U2 = z2 * Ld2 + z3 * L32;
        float U3 = z3 * Ld3;
        float Ua0 = __shfl_sync(FULLMASK, U0, q);
        float Ua1 = __shfl_sync(FULLMASK, U1, q);
        float Ua2 = __shfl_sync(FULLMASK, U2, q);
        float Ua3 = __shfl_sync(FULLMASK, U3, q);
        float Ub0 = __shfl_sync(FULLMASK, U0, q + 4);
        float Ub1 = __shfl_sync(FULLMASK, U1, q + 4);
        float Ub2 = __shfl_sync(FULLMASK, U2, q + 4);
        float Ub3 = __shfl_sync(FULLMASK, U3, q + 4);
        float p1 = ppa - (Ua0 * U0 + Ua1 * U1 + Ua2 * U2 + Ua3 * U3) + ((i1 == o) ? JIT : 0.0f);
        float p2 = ppb - (Ub0 * U0 + Ub1 * U1 + Ub2 * U2 + Ub3 * U3) + ((i2 == o) ? JIT : 0.0f);
        sP[i1 * 9 + o] = p1;
        sP[i2 * 9 + o] = p2;
        long bp = ((long)b * T + t) * 64;
        outP[bp + i1 * 8 + o] = p1;
        outP[bp + i2 * 8 + o] = p2;
        __syncwarp();
    }

    // ==== epilogue: q_e[T-1] from final P_pred ====
    {
        float a[8];
        #pragma unroll
        for (int c = 0; c < 8; ++c) a[c] = sPp[o * 9 + c];
        float md = 1.0f;
        #pragma unroll
        for (int k = 0; k < 8; ++k) {
            float akk = __shfl_sync(FULLMASK, a[k], k);
            float inv = rsqrtf(akk);
            float lk = a[k] * inv;
            if (o == k) { a[k] = akk * inv; md = a[k]; }
            else if (o > k) a[k] = lk;
            #pragma unroll
            for (int jj = k + 1; jj < 8; ++jj) {
                float lj = __shfl_sync(FULLMASK, a[k], jj);
                if (o >= jj) a[jj] -= a[k] * lj;
            }
        }
        float lg = __logf(md);
        lg += __shfl_xor_sync(FULLMASK, lg, 1);
        lg += __shfl_xor_sync(FULLMASK, lg, 2);
        lg += __shfl_xor_sync(FULLMASK, lg, 4);
        if (lane == 0) outQ[(long)b * T + (T - 1)] = lg;
    }
}

extern "C" void kernel_launch(void* const* d_in, const int* in_sizes, int n_in,
                              void* d_out, int out_size) {
    const float* X0  = (const float*)d_in[0];
    const float* u   = (const float*)d_in[1];
    const float* yv  = (const float*)d_in[2];
    const float* W1  = (const float*)d_in[3];
    const float* b1  = (const float*)d_in[4];
    const float* W2  = (const float*)d_in[5];
    const float* b2  = (const float*)d_in[6];
    const float* Hm  = (const float*)d_in[7];
    const float* lq  = (const float*)d_in[8];
    const float* lr  = (const float*)d_in[9];
    const float* lp0 = (const float*)d_in[10];

    const int B = in_sizes[0] / 8;                 // 1024
    const int T = in_sizes[1] / (B * 2);           // 256

    float* out  = (float*)d_out;
    float* outX = out;
    float* outP = out + (long)B * T * 8;
    float* outQ = out + (long)B * T * (8 + 64);
    float* outR = outQ + (long)B * T;

    ukf_kernel<<<B, 32>>>(X0, u, yv, W1, b1, W2, b2, Hm, lq, lr, lp0,
                          outX, outP, outQ, outR, T);
}

// round 8
// speedup vs baseline: 1.4066x; 1.1550x over previous
#include <cuda_runtime.h>

#define FULLMASK 0xffffffffu

__device__ __forceinline__ float ftanh(float x) {
    float y;
    asm("tanh.approx.f32 %0, %1;" : "=f"(y) : "f"(x));
    return y;
}
__device__ __forceinline__ float softplusf(float x) {
    return log1pf(__expf(x));
}

// One warp per batch element. Warp-synchronous UKF with root-free (LDL) Cholesky.
__global__ void __launch_bounds__(32) ukf_kernel(
    const float* __restrict__ X0, const float* __restrict__ u, const float* __restrict__ yy,
    const float* __restrict__ W1, const float* __restrict__ b1,
    const float* __restrict__ W2, const float* __restrict__ b2,
    const float* __restrict__ Hm, const float* __restrict__ lq,
    const float* __restrict__ lr, const float* __restrict__ lp0,
    float* __restrict__ outX, float* __restrict__ outP,
    float* __restrict__ outQ, float* __restrict__ outR,
    int T)
{
    const float JIT = 1e-4f;
    const int b = blockIdx.x;
    const int lane = threadIdx.x;

    __shared__ __align__(16) float sP[64];         // P_new (8x8, stride 8)
    __shared__ __align__(16) float sPp[64];        // P_pred (8x8, stride 8)
    __shared__ __align__(16) float sHid[17 * 36];  // tanh activations
    __shared__ __align__(16) float sDxT[8 * 20];   // dx transposed [col][s]

    const int o  = lane & 7;    // state index
    const int q  = lane >> 3;   // sigma group / P row base
    const int m  = lane & 3;    // measurement index
    const int pn = lane >> 2;   // Pxy row
    const int si = pn & 3;      // Sy row index
    const int i1 = q, i2 = q + 4;
    const int g8 = lane & 8;    // dual-chol shuffle base
    const int b4 = lane & 28;   // 4-group base
    const int r4 = lane & 3;    // Sy chol row

    // ---- persistent per-lane weights in registers ----
    float w1c[10];
    #pragma unroll
    for (int d = 0; d < 10; ++d) w1c[d] = W1[d * 32 + lane];
    float b1v = b1[lane];
    float w2c[32];
    #pragma unroll
    for (int h = 0; h < 32; ++h) w2c[h] = W2[h * 8 + o];
    float b2o = b2[o];
    float hmr[8];
    #pragma unroll
    for (int d = 0; d < 8; ++d) hmr[d] = Hm[m * 8 + d];
    float hsr[8];
    #pragma unroll
    for (int d = 0; d < 8; ++d) hsr[d] = Hm[si * 8 + d];

    const float cD1 = (i1 == o) ? (softplusf(lq[i1]) + JIT) : 0.0f;
    const float cD2 = (i2 == o) ? (softplusf(lq[i2]) + JIT) : 0.0f;
    const float radd = (si == m) ? softplusf(lr[si]) : 0.0f;
    const float corrP = (softplusf(lq[pn]) + JIT) * Hm[m * 8 + pn];  // Pxy diag fix

    // ---- init: t=0 outputs, P0, identity Pp ----
    float xreg = X0[b * 8 + o];
    if (lane < 8) outX[(long)b * T * 8 + lane] = xreg;
    #pragma unroll
    for (int rep = 0; rep < 2; ++rep) {
        int idx = lane + 32 * rep;
        int ii = idx >> 3, jj = idx & 7;
        float pv = (ii == jj) ? softplusf(lp0[ii]) : 0.0f;
        sP[idx] = pv;
        sPp[idx] = (ii == jj) ? 1.0f : 0.0f;
        outP[(long)b * T * 64 + idx] = pv;
    }
    if (lane == 0) { outQ[(long)b * T] = 0.0f; outR[(long)b * T] = 0.0f; }
    __syncwarp();

    for (int t = 1; t < T; ++t) {
        // ---- early loads (off critical path) ----
        const float2 uv = *reinterpret_cast<const float2*>(&u[((long)b * T + (t - 1)) * 2]);
        const float yraw = yy[((long)b * T + t) * 4 + m];

        // ---- hidden-layer base (independent of chol; hoisted) ----
        float bx;
        {
            float ba = b1v + uv.x * w1c[8];
            float bb = uv.y * w1c[9];
            #pragma unroll
            for (int d = 0; d < 8; d += 2) {
                ba += __shfl_sync(FULLMASK, xreg, d) * w1c[d];
                bb += __shfl_sync(FULLMASK, xreg, d + 1) * w1c[d + 1];
            }
            bx = ba + bb;
        }

        // ==== dual LDL chol: bit3=0 -> A=8P+JIT*I ; bit3=1 -> Pp_prev ====
        float a[8];
        {
            const float4* srcp = reinterpret_cast<const float4*>(g8 ? &sPp[o * 8] : &sP[o * 8]);
            float4 r0 = srcp[0], r1 = srcp[1];
            a[0] = r0.x; a[1] = r0.y; a[2] = r0.z; a[3] = r0.w;
            a[4] = r1.x; a[5] = r1.y; a[6] = r1.z; a[7] = r1.w;
            if (!g8) {
                #pragma unroll
                for (int c = 0; c < 8; ++c)
                    a[c] = 8.0f * a[c] + ((c == o) ? JIT : 0.0f);
            }
        }
        float invsq[8];
        float myd = 1.0f;
        #pragma unroll
        for (int k = 0; k < 8; ++k) {
            float dk = __shfl_sync(FULLMASK, a[k], g8 + k);   // own-group raw pivot
            float isq = rsqrtf(dk);
            invsq[k] = isq;
            float rc = isq * isq;                              // 1/d_k
            myd = (o == k) ? dk : myd;
            float tt = a[k] * rc;
            #pragma unroll
            for (int jj = k + 1; jj < 8; ++jj) {
                float lj = __shfl_sync(FULLMASK, a[k], g8 + jj);  // raw, prev-iter value
                a[jj] -= tt * lj;
            }
        }
        // deferred q_e of previous step (lanes 8-15 hold pivots of Pp_prev)
        {
            float lg = __logf(myd);
            lg += __shfl_xor_sync(FULLMASK, lg, 1);
            lg += __shfl_xor_sync(FULLMASK, lg, 2);
            lg += __shfl_xor_sync(FULLMASK, lg, 4);
            if (lane == 8 && t >= 2) outQ[(long)b * T + (t - 1)] = 0.5f * lg;
        }
        // CRITICAL: broadcast A-factorization invsq to ALL lanes (lane 0 is g8=0).
        #pragma unroll
        for (int k = 0; k < 8; ++k)
            invsq[k] = __shfl_sync(FULLMASK, invsq[k], 0);
        // true L row o of A (normalize lazily); zeros above diagonal
        float Lrow[8];
        #pragma unroll
        for (int i = 0; i < 8; ++i) {
            float lv = __shfl_sync(FULLMASK, a[i], o);
            Lrow[i] = (i <= o) ? lv * invsq[i] : 0.0f;
        }
        // G[i] = invsq[i] * sum_{d>=i} raw[d][i]*w1c[d]  (raw from lanes 0-7 = A group)
        float G[8];
        #pragma unroll
        for (int i = 0; i < 8; ++i) {
            float g = 0.0f;
            #pragma unroll
            for (int d = i; d < 8; ++d)
                g += __shfl_sync(FULLMASK, a[i], d) * w1c[d];
            G[i] = g * invsq[i];
        }

        sHid[0 * 36 + lane] = ftanh(bx);
        #pragma unroll
        for (int i = 0; i < 8; ++i) {
            sHid[(1 + i) * 36 + lane] = ftanh(bx + G[i]);
            sHid[(9 + i) * 36 + lane] = ftanh(bx - G[i]);
        }
        __syncwarp();

        // ==== output layer + x_pred + dx (stored transposed) ====
        float pf[5];
        float xsum = 0.0f;
        #pragma unroll
        for (int g = 0; g < 5; ++g) {
            int s = 4 * g + q;
            bool valid = (s < 17);
            int ss = valid ? s : 0;
            const float4* hp = reinterpret_cast<const float4*>(&sHid[ss * 36]);
            float ea = 0.0f, eb = 0.0f;
            #pragma unroll
            for (int hh = 0; hh < 8; ++hh) {
                float4 hv = hp[hh];
                ea += hv.x * w2c[4 * hh] + hv.y * w2c[4 * hh + 1];
                eb += hv.z * w2c[4 * hh + 2] + hv.w * w2c[4 * hh + 3];
            }
            float e = b2o + ea + eb;
            float delta = 0.0f;
            if (ss >= 1 && ss <= 8) delta = Lrow[ss - 1];
            else if (ss >= 9)       delta = -Lrow[ss - 9];
            float p = xreg + delta + e;
            pf[g] = p;
            if (valid && s >= 1) xsum += p;      // Wm[0] = 0
        }
        xsum += __shfl_xor_sync(FULLMASK, xsum, 8);
        xsum += __shfl_xor_sync(FULLMASK, xsum, 16);
        const float xpred = xsum * 0.0625f;
        #pragma unroll
        for (int g = 0; g < 5; ++g) {
            int s = 4 * g + q;
            if (s < 17) sDxT[o * 20 + s] = pf[g] - xpred;
        }
        __syncwarp();

        // ==== Cx (16x scaled): a1=16*Cx[i1][o], a2=16*Cx[i2][o], dual accumulators ====
        float a1, a2;
        {
            const float4* cq = reinterpret_cast<const float4*>(&sDxT[i1 * 20]);
            const float4* c2 = reinterpret_cast<const float4*>(&sDxT[i2 * 20]);
            const float4* co = reinterpret_cast<const float4*>(&sDxT[o * 20]);
            float4 xq = cq[0], x2 = c2[0], xo = co[0];
            float a1a = 32.0f * xq.x * xo.x + xq.y * xo.y;   // Wc0 = 2 = 32/16
            float a1b = xq.z * xo.z + xq.w * xo.w;
            float a2a = 32.0f * x2.x * xo.x + x2.y * xo.y;
            float a2b = x2.z * xo.z + x2.w * xo.w;
            #pragma unroll
            for (int c = 1; c < 4; ++c) {
                xq = cq[c]; x2 = c2[c]; xo = co[c];
                a1a += xq.x * xo.x + xq.y * xo.y;
                a1b += xq.z * xo.z + xq.w * xo.w;
                a2a += x2.x * xo.x + x2.y * xo.y;
                a2b += x2.z * xo.z + x2.w * xo.w;
            }
            float q16 = sDxT[i1 * 20 + 16], t16 = sDxT[i2 * 20 + 16], o16 = sDxT[o * 20 + 16];
            a1 = a1a + a1b + q16 * o16;
            a2 = a2a + a2b + t16 * o16;
        }
        const float ppa = a1 * 0.0625f + cD1;   // P_pred[i1][o]
        const float ppb = a2 * 0.0625f + cD2;   // P_pred[i2][o]
        sPp[i1 * 8 + o] = ppa;
        sPp[i2 * 8 + o] = ppb;
        __syncwarp();

        // ==== Pxy[pn][m] = (P_pred - diag(Q+JIT)) row_pn . Hm row_m ====
        float pxy;
        {
            const float4* pr = reinterpret_cast<const float4*>(&sPp[pn * 8]);
            float4 p0 = pr[0], p1v = pr[1];
            float pa = p0.x * hmr[0] + p0.y * hmr[1] + p0.z * hmr[2];
            float pb = p0.w * hmr[3] + p1v.x * hmr[4] + p1v.y * hmr[5];
            float pc = p1v.z * hmr[6] + p1v.w * hmr[7] - corrP;
            pxy = pa + pb + pc;
        }
        // ==== Sy[si][m] = Hm row_si . Pxy col_m + R ====
        float syv;
        {
            float sa = radd, sb = 0.0f;
            #pragma unroll
            for (int d = 0; d < 8; d += 2) {
                sa += hsr[d] * __shfl_sync(FULLMASK, pxy, d * 4 + m);
                sb += hsr[d + 1] * __shfl_sync(FULLMASK, pxy, (d + 1) * 4 + m);
            }
            syv = sa + sb;
        }

        // ==== Sy 4x4 root-free LDL (4-lane groups; all groups factor same Sy) ====
        float s4[4];
        #pragma unroll
        for (int c = 0; c < 4; ++c)
            s4[c] = __shfl_sync(FULLMASK, syv, r4 * 4 + c);
        float isq4[4], rec4[4], dk4[4];
        float myd4 = 1.0f;
        #pragma unroll
        for (int k = 0; k < 4; ++k) {
            float dk = __shfl_sync(FULLMASK, s4[k], b4 + k);
            float is = rsqrtf(dk);
            isq4[k] = is;
            float rc = is * is;
            rec4[k] = rc;
            dk4[k] = dk;
            myd4 = (r4 == k) ? dk : myd4;
            float tt = s4[k] * rc;
            #pragma unroll
            for (int jj = k + 1; jj < 4; ++jj) {
                float lj = __shfl_sync(FULLMASK, s4[k], b4 + jj);
                s4[jj] -= tt * lj;
            }
        }
        {
            float lg = __logf(myd4);
            lg += __shfl_xor_sync(FULLMASK, lg, 1);
            lg += __shfl_xor_sync(FULLMASK, lg, 2);
            if (lane == 0) outR[(long)b * T + t] = 0.5f * lg;
        }
        // raw L-tilde pieces
        const float L10 = __shfl_sync(FULLMASK, s4[0], b4 + 1);
        const float L20 = __shfl_sync(FULLMASK, s4[0], b4 + 2);
        const float L30 = __shfl_sync(FULLMASK, s4[0], b4 + 3);
        const float L21 = __shfl_sync(FULLMASK, s4[1], b4 + 2);
        const float L31 = __shfl_sync(FULLMASK, s4[1], b4 + 3);
        const float L32 = __shfl_sync(FULLMASK, s4[2], b4 + 3);

        // ==== K row o: LDL solve  Sy x = Pxy_row_o ====
        float w0 = __shfl_sync(FULLMASK, pxy, o * 4 + 0);
        float w1 = __shfl_sync(FULLMASK, pxy, o * 4 + 1);
        float w2 = __shfl_sync(FULLMASK, pxy, o * 4 + 2);
        float w3 = __shfl_sync(FULLMASK, pxy, o * 4 + 3);
        float v0 = rec4[0] * w0;
        float v1 = rec4[1] * (w1 - L10 * v0);
        float v2 = rec4[2] * (w2 - L20 * v0 - L21 * v1);
        float v3 = rec4[3] * (w3 - L30 * v0 - L31 * v1 - L32 * v2);
        float z3 = v3;
        float z2 = v2 - rec4[2] * (L32 * z3);
        float z1 = v1 - rec4[1] * (L21 * z2 + L31 * z3);
        float z0 = v0 - rec4[0] * (L10 * z1 + L20 * z2 + L30 * z3);

        // ==== innovation & state update ====
        float inno;
        {
            float ya = 0.0f, yb = 0.0f;
            #pragma unroll
            for (int d = 0; d < 8; d += 2) {
                ya += hmr[d] * __shfl_sync(FULLMASK, xpred, d);
                yb += hmr[d + 1] * __shfl_sync(FULLMASK, xpred, d + 1);
            }
            inno = yraw - (ya + yb);
        }
        const float in0 = __shfl_sync(FULLMASK, inno, b4 + 0);
        const float in1 = __shfl_sync(FULLMASK, inno, b4 + 1);
        const float in2 = __shfl_sync(FULLMASK, inno, b4 + 2);
        const float in3 = __shfl_sync(FULLMASK, inno, b4 + 3);
        float xn = xpred + z0 * in0 + z1 * in1 + z2 * in2 + z3 * in3;
        xreg = xn;
        if (lane < 8) outX[((long)b * T + t) * 8 + o] = xn;

        // ==== U = K * L(Sy) (true), P_new = Ppred - U U^T + JIT*I (bitwise symmetric) ====
        float U0 = (z0 * dk4[0] + z1 * L10 + z2 * L20 + z3 * L30) * isq4[0];
        float U1 = (z1 * dk4[1] + z2 * L21 + z3 * L31) * isq4[1];
        float U2 = (z2 * dk4[2] + z3 * L32) * isq4[2];
        float U3 = (z3 * dk4[3]) * isq4[3];
        float Ua0 = __shfl_sync(FULLMASK, U0, q);
        float Ua1 = __shfl_sync(FULLMASK, U1, q);
        float Ua2 = __shfl_sync(FULLMASK, U2, q);
        float Ua3 = __shfl_sync(FULLMASK, U3, q);
        float Ub0 = __shfl_sync(FULLMASK, U0, q + 4);
        float Ub1 = __shfl_sync(FULLMASK, U1, q + 4);
        float Ub2 = __shfl_sync(FULLMASK, U2, q + 4);
        float Ub3 = __shfl_sync(FULLMASK, U3, q + 4);
        float p1 = ppa - (Ua0 * U0 + Ua1 * U1 + Ua2 * U2 + Ua3 * U3) + ((i1 == o) ? JIT : 0.0f);
        float p2 = ppb - (Ub0 * U0 + Ub1 * U1 + Ub2 * U2 + Ub3 * U3) + ((i2 == o) ? JIT : 0.0f);
        sP[i1 * 8 + o] = p1;
        sP[i2 * 8 + o] = p2;
        long bp = ((long)b * T + t) * 64;
        outP[bp + i1 * 8 + o] = p1;
        outP[bp + i2 * 8 + o] = p2;
        __syncwarp();
    }

    // ==== epilogue: q_e[T-1] from final P_pred (root-free pivots) ====
    {
        float a[8];
        #pragma unroll
        for (int c = 0; c < 8; ++c) a[c] = sPp[o * 8 + c];
        float myd = 1.0f;
        #pragma unroll
        for (int k = 0; k < 8; ++k) {
            float dk = __shfl_sync(FULLMASK, a[k], k);
            float isq = rsqrtf(dk);
            float rc = isq * isq;
            myd = (o == k) ? dk : myd;
            float tt = a[k] * rc;
            #pragma unroll
            for (int jj = k + 1; jj < 8; ++jj) {
                float lj = __shfl_sync(FULLMASK, a[k], jj);
                a[jj] -= tt * lj;
            }
        }
        float lg = __logf(myd);
        lg += __shfl_xor_sync(FULLMASK, lg, 1);
        lg += __shfl_xor_sync(FULLMASK, lg, 2);
        lg += __shfl_xor_sync(FULLMASK, lg, 4);
        if (lane == 0) outQ[(long)b * T + (T - 1)] = 0.5f * lg;
    }
}

extern "C" void kernel_launch(void* const* d_in, const int* in_sizes, int n_in,
                              void* d_out, int out_size) {
    const float* X0  = (const float*)d_in[0];
    const float* u   = (const float*)d_in[1];
    const float* yv  = (const float*)d_in[2];
    const float* W1  = (const float*)d_in[3];
    const float* b1  = (const float*)d_in[4];
    const float* W2  = (const float*)d_in[5];
    const float* b2  = (const float*)d_in[6];
    const float* Hm  = (const float*)d_in[7];
    const float* lq  = (const float*)d_in[8];
    const float* lr  = (const float*)d_in[9];
    const float* lp0 = (const float*)d_in[10];

    const int B = in_sizes[0] / 8;                 // 1024
    const int T = in_sizes[1] / (B * 2);           // 256

    float* out  = (float*)d_out;
    float* outX = out;
    float* outP = out + (long)B * T * 8;
    float* outQ = out + (long)B * T * (8 + 64);
    float* outR = outQ + (long)B * T;

    ukf_kernel<<<B, 32>>>(X0, u, yv, W1, b1, W2, b2, Hm, lq, lr, lp0,
                          outX, outP, outQ, outR, T);
}

// round 9
// speedup vs baseline: 1.4627x; 1.0399x over previous
#include <cuda_runtime.h>

#define FULLMASK 0xffffffffu

__device__ __forceinline__ float ftanh(float x) {
    float y;
    asm("tanh.approx.f32 %0, %1;" : "=f"(y) : "f"(x));
    return y;
}
__device__ __forceinline__ float softplusf(float x) {
    return log1pf(__expf(x));
}

// One warp per batch element. Warp-synchronous UKF, LDL 8x8 chol + cofactor 4x4 inverse.
__global__ void __launch_bounds__(32) ukf_kernel(
    const float* __restrict__ X0, const float* __restrict__ u, const float* __restrict__ yy,
    const float* __restrict__ W1, const float* __restrict__ b1,
    const float* __restrict__ W2, const float* __restrict__ b2,
    const float* __restrict__ Hm, const float* __restrict__ lq,
    const float* __restrict__ lr, const float* __restrict__ lp0,
    float* __restrict__ outX, float* __restrict__ outP,
    float* __restrict__ outQ, float* __restrict__ outR,
    int T)
{
    const float JIT = 1e-4f;
    const int b = blockIdx.x;
    const int lane = threadIdx.x;

    __shared__ __align__(16) float sP[64];         // P_new (8x8, stride 8)
    __shared__ __align__(16) float sPp[64];        // P_pred (8x8, stride 8)
    __shared__ __align__(16) float sHid[17 * 36];  // tanh activations
    __shared__ __align__(16) float sDxT[8 * 20];   // dx transposed [col][s]
    __shared__ __align__(16) float sX[8];          // current state
    __shared__ __align__(16) float sXp[8];         // x_pred

    const int o  = lane & 7;    // state index
    const int q  = lane >> 3;   // sigma group / P row base
    const int m  = lane & 3;    // measurement index
    const int pn = lane >> 2;   // Pxy row
    const int si = pn & 3;      // Sy row index
    const int i1 = q, i2 = q + 4;
    const int g8 = lane & 8;    // dual-chol shuffle base
    const int b4 = lane & 28;   // 4-group base

    // ---- persistent per-lane weights in registers ----
    float w1c[10];
    #pragma unroll
    for (int d = 0; d < 10; ++d) w1c[d] = W1[d * 32 + lane];
    float b1v = b1[lane];
    float w2c[32];
    #pragma unroll
    for (int h = 0; h < 32; ++h) w2c[h] = W2[h * 8 + o];
    float b2o = b2[o];
    float hmr[8];
    #pragma unroll
    for (int d = 0; d < 8; ++d) hmr[d] = Hm[m * 8 + d];
    float hsr[8];
    #pragma unroll
    for (int d = 0; d < 8; ++d) hsr[d] = Hm[si * 8 + d];

    const float cD1 = (i1 == o) ? (softplusf(lq[i1]) + JIT) : 0.0f;
    const float cD2 = (i2 == o) ? (softplusf(lq[i2]) + JIT) : 0.0f;
    const float radd = (si == m) ? softplusf(lr[si]) : 0.0f;
    const float corrP = (softplusf(lq[pn]) + JIT) * Hm[m * 8 + pn];  // Pxy diag fix

    // ---- init: t=0 outputs, P0, identity Pp ----
    float xreg = X0[b * 8 + o];
    if (lane < 8) { sX[lane] = xreg; outX[(long)b * T * 8 + lane] = xreg; }
    #pragma unroll
    for (int rep = 0; rep < 2; ++rep) {
        int idx = lane + 32 * rep;
        int ii = idx >> 3, jj = idx & 7;
        float pv = (ii == jj) ? softplusf(lp0[ii]) : 0.0f;
        sP[idx] = pv;
        sPp[idx] = (ii == jj) ? 1.0f : 0.0f;
        outP[(long)b * T * 64 + idx] = pv;
    }
    if (lane == 0) { outQ[(long)b * T] = 0.0f; outR[(long)b * T] = 0.0f; }
    __syncwarp();

    for (int t = 1; t < T; ++t) {
        // ---- early loads (off critical path) ----
        const float2 uv = *reinterpret_cast<const float2*>(&u[((long)b * T + (t - 1)) * 2]);
        const float yraw = yy[((long)b * T + t) * 4 + m];

        // ---- hidden-layer base from sX (2 LDS.128) ----
        float bx;
        {
            const float4* xp4 = reinterpret_cast<const float4*>(sX);
            float4 x0 = xp4[0], x1 = xp4[1];
            float ba = b1v + uv.x * w1c[8] + x0.x * w1c[0] + x0.y * w1c[1] + x0.z * w1c[2];
            float bb = uv.y * w1c[9] + x0.w * w1c[3] + x1.x * w1c[4] + x1.y * w1c[5];
            bx = ba + bb + x1.z * w1c[6] + x1.w * w1c[7];
        }

        // ==== dual LDL chol: bit3=0 -> A=8P+JIT*I ; bit3=1 -> Pp_prev ====
        float a[8];
        {
            const float4* srcp = reinterpret_cast<const float4*>(g8 ? &sPp[o * 8] : &sP[o * 8]);
            float4 r0 = srcp[0], r1 = srcp[1];
            a[0] = r0.x; a[1] = r0.y; a[2] = r0.z; a[3] = r0.w;
            a[4] = r1.x; a[5] = r1.y; a[6] = r1.z; a[7] = r1.w;
            if (!g8) {
                #pragma unroll
                for (int c = 0; c < 8; ++c)
                    a[c] = 8.0f * a[c] + ((c == o) ? JIT : 0.0f);
            }
        }
        float invsq[8];
        float myd = 1.0f;
        #pragma unroll
        for (int k = 0; k < 8; ++k) {
            float dk = __shfl_sync(FULLMASK, a[k], g8 + k);   // own-group raw pivot
            float isq = rsqrtf(dk);
            invsq[k] = isq;
            float rc = isq * isq;                              // 1/d_k
            myd = (o == k) ? dk : myd;
            float tt = a[k] * rc;
            #pragma unroll
            for (int jj = k + 1; jj < 8; ++jj) {
                float lj = __shfl_sync(FULLMASK, a[k], g8 + jj);  // raw, prev-iter value
                a[jj] -= tt * lj;
            }
        }
        // deferred q_e of previous step (lanes 8-15 hold pivots of Pp_prev)
        {
            float lg = __logf(myd);
            lg += __shfl_xor_sync(FULLMASK, lg, 1);
            lg += __shfl_xor_sync(FULLMASK, lg, 2);
            lg += __shfl_xor_sync(FULLMASK, lg, 4);
            if (lane == 8 && t >= 2) outQ[(long)b * T + (t - 1)] = 0.5f * lg;
        }
        // broadcast A-factorization invsq to ALL lanes (lane 0 is g8=0)
        #pragma unroll
        for (int k = 0; k < 8; ++k)
            invsq[k] = __shfl_sync(FULLMASK, invsq[k], 0);
        // true L row o of A (normalize lazily); zeros above diagonal
        float Lrow[8];
        #pragma unroll
        for (int i = 0; i < 8; ++i) {
            float lv = __shfl_sync(FULLMASK, a[i], o);
            Lrow[i] = (i <= o) ? lv * invsq[i] : 0.0f;
        }
        // G[i] = invsq[i] * sum_{d>=i} raw[d][i]*w1c[d]
        float G[8];
        #pragma unroll
        for (int i = 0; i < 8; ++i) {
            float g = 0.0f;
            #pragma unroll
            for (int d = i; d < 8; ++d)
                g += __shfl_sync(FULLMASK, a[i], d) * w1c[d];
            G[i] = g * invsq[i];
        }

        sHid[0 * 36 + lane] = ftanh(bx);
        #pragma unroll
        for (int i = 0; i < 8; ++i) {
            sHid[(1 + i) * 36 + lane] = ftanh(bx + G[i]);
            sHid[(9 + i) * 36 + lane] = ftanh(bx - G[i]);
        }
        __syncwarp();

        // ==== output layer + x_pred + dx (stored transposed) ====
        float pf[5];
        float xsum = 0.0f;
        #pragma unroll
        for (int g = 0; g < 5; ++g) {
            int s = 4 * g + q;
            bool valid = (s < 17);
            int ss = valid ? s : 0;
            const float4* hp = reinterpret_cast<const float4*>(&sHid[ss * 36]);
            float ea = 0.0f, eb = 0.0f;
            #pragma unroll
            for (int hh = 0; hh < 8; ++hh) {
                float4 hv = hp[hh];
                ea += hv.x * w2c[4 * hh] + hv.y * w2c[4 * hh + 1];
                eb += hv.z * w2c[4 * hh + 2] + hv.w * w2c[4 * hh + 3];
            }
            float e = b2o + ea + eb;
            float delta = 0.0f;
            if (ss >= 1 && ss <= 8) delta = Lrow[ss - 1];
            else if (ss >= 9)       delta = -Lrow[ss - 9];
            float p = xreg + delta + e;
            pf[g] = p;
            if (valid && s >= 1) xsum += p;      // Wm[0] = 0
        }
        xsum += __shfl_xor_sync(FULLMASK, xsum, 8);
        xsum += __shfl_xor_sync(FULLMASK, xsum, 16);
        const float xpred = xsum * 0.0625f;
        if (lane < 8) sXp[o] = xpred;
        #pragma unroll
        for (int g = 0; g < 5; ++g) {
            int s = 4 * g + q;
            if (s < 17) sDxT[o * 20 + s] = pf[g] - xpred;
        }
        __syncwarp();

        // ==== Cx (16x scaled): a1=16*Cx[i1][o], a2=16*Cx[i2][o], dual accumulators ====
        float a1, a2;
        {
            const float4* cq = reinterpret_cast<const float4*>(&sDxT[i1 * 20]);
            const float4* c2 = reinterpret_cast<const float4*>(&sDxT[i2 * 20]);
            const float4* co = reinterpret_cast<const float4*>(&sDxT[o * 20]);
            float4 xq = cq[0], x2 = c2[0], xo = co[0];
            float a1a = 32.0f * xq.x * xo.x + xq.y * xo.y;   // Wc0 = 2 = 32/16
            float a1b = xq.z * xo.z + xq.w * xo.w;
            float a2a = 32.0f * x2.x * xo.x + x2.y * xo.y;
            float a2b = x2.z * xo.z + x2.w * xo.w;
            #pragma unroll
            for (int c = 1; c < 4; ++c) {
                xq = cq[c]; x2 = c2[c]; xo = co[c];
                a1a += xq.x * xo.x + xq.y * xo.y;
                a1b += xq.z * xo.z + xq.w * xo.w;
                a2a += x2.x * xo.x + x2.y * xo.y;
                a2b += x2.z * xo.z + x2.w * xo.w;
            }
            float q16 = sDxT[i1 * 20 + 16], t16 = sDxT[i2 * 20 + 16], o16 = sDxT[o * 20 + 16];
            a1 = a1a + a1b + q16 * o16;
            a2 = a2a + a2b + t16 * o16;
        }
        const float ppa = a1 * 0.0625f + cD1;   // P_pred[i1][o]
        const float ppb = a2 * 0.0625f + cD2;   // P_pred[i2][o]
        sPp[i1 * 8 + o] = ppa;
        sPp[i2 * 8 + o] = ppb;
        __syncwarp();

        // ==== Pxy[pn][m] = (P_pred - diag(Q+JIT)) row_pn . Hm row_m ====
        float pxy;
        {
            const float4* pr = reinterpret_cast<const float4*>(&sPp[pn * 8]);
            float4 p0 = pr[0], p1v = pr[1];
            float pa = p0.x * hmr[0] + p0.y * hmr[1] + p0.z * hmr[2];
            float pb = p0.w * hmr[3] + p1v.x * hmr[4] + p1v.y * hmr[5];
            float pc = p1v.z * hmr[6] + p1v.w * hmr[7] - corrP;
            pxy = pa + pb + pc;
        }
        // ==== Sy[si][m] = Hm row_si . Pxy col_m + R ====
        float syv;
        {
            float sa = radd, sb = 0.0f;
            #pragma unroll
            for (int d = 0; d < 8; d += 2) {
                sa += hsr[d] * __shfl_sync(FULLMASK, pxy, d * 4 + m);
                sb += hsr[d + 1] * __shfl_sync(FULLMASK, pxy, (d + 1) * 4 + m);
            }
            syv = sa + sb;
        }

        // ==== gather the 10 unique Sy entries to every lane ====
        const float Saa = __shfl_sync(FULLMASK, syv, 0);
        const float Sab = __shfl_sync(FULLMASK, syv, 1);
        const float Sac = __shfl_sync(FULLMASK, syv, 2);
        const float Sad = __shfl_sync(FULLMASK, syv, 3);
        const float Sbb = __shfl_sync(FULLMASK, syv, 5);
        const float Sbc = __shfl_sync(FULLMASK, syv, 6);
        const float Sbd = __shfl_sync(FULLMASK, syv, 7);
        const float Scc = __shfl_sync(FULLMASK, syv, 10);
        const float Scd = __shfl_sync(FULLMASK, syv, 11);
        const float Sdd = __shfl_sync(FULLMASK, syv, 15);

        // ==== closed-form symmetric 4x4 inverse (Mesa 2x2-subdet scheme) ====
        const float s0 = Saa * Sbb - Sab * Sab;
        const float s1 = Saa * Sbc - Sab * Sac;
        const float s2 = Saa * Sbd - Sab * Sad;
        const float s3 = Sab * Sbc - Sbb * Sac;
        const float s4 = Sab * Sbd - Sbb * Sad;
        const float s5 = Sac * Sbd - Sbc * Sad;
        const float c5 = Scc * Sdd - Scd * Scd;
        const float c4 = Sbc * Sdd - Sbd * Scd;
        const float c3 = Sbc * Scd - Sbd * Scc;
        const float c2 = Sac * Sdd - Sad * Scd;
        const float c1 = Sac * Scd - Sad * Scc;
        const float c0 = s5;                     // == Sac*Sbd - Sad*Sbc
        const float det = s0 * c5 - s1 * c4 + s2 * c3 + s3 * c2 - s4 * c1 + s5 * c0;
        const float rdet = __fdividef(1.0f, det);
        if (lane == 0) outR[(long)b * T + t] = 0.5f * __logf(det);
        // adjugate (symmetric, upper triangle)
        const float A00 =  Sbb * c5 - Sbc * c4 + Sbd * c3;
        const float A01 = -Sab * c5 + Sac * c4 - Sad * c3;
        const float A02 =  Sbd * s5 - Scd * s4 + Sdd * s3;
        const float A03 = -Sbc * s5 + Scc * s4 - Scd * s3;
        const float A11 =  Saa * c5 - Sac * c2 + Sad * c1;
        const float A12 = -Sad * s5 + Scd * s2 - Sdd * s1;
        const float A13 =  Sac * s5 - Scc * s2 + Scd * s1;
        const float A22 =  Sad * s4 - Sbd * s2 + Sdd * s0;
        const float A23 = -Sac * s4 + Sbc * s2 - Scd * s0;
        const float A33 =  Sac * s3 - Sbc * s1 + Scc * s0;

        // ==== K row o = Pxy row o * Sinv ====
        const float w0 = __shfl_sync(FULLMASK, pxy, o * 4 + 0);
        const float w1 = __shfl_sync(FULLMASK, pxy, o * 4 + 1);
        const float w2 = __shfl_sync(FULLMASK, pxy, o * 4 + 2);
        const float w3 = __shfl_sync(FULLMASK, pxy, o * 4 + 3);
        const float z0 = (w0 * A00 + w1 * A01 + w2 * A02 + w3 * A03) * rdet;
        const float z1 = (w0 * A01 + w1 * A11 + w2 * A12 + w3 * A13) * rdet;
        const float z2 = (w0 * A02 + w1 * A12 + w2 * A22 + w3 * A23) * rdet;
        const float z3 = (w0 * A03 + w1 * A13 + w2 * A23 + w3 * A33) * rdet;

        // ==== innovation (from sXp) & state update ====
        float inno;
        {
            const float4* xp4 = reinterpret_cast<const float4*>(sXp);
            float4 x0 = xp4[0], x1 = xp4[1];
            float ya = hmr[0] * x0.x + hmr[1] * x0.y + hmr[2] * x0.z + hmr[3] * x0.w;
            float yb = hmr[4] * x1.x + hmr[5] * x1.y + hmr[6] * x1.z + hmr[7] * x1.w;
            inno = yraw - (ya + yb);
        }
        const float in0 = __shfl_sync(FULLMASK, inno, b4 + 0);
        const float in1 = __shfl_sync(FULLMASK, inno, b4 + 1);
        const float in2 = __shfl_sync(FULLMASK, inno, b4 + 2);
        const float in3 = __shfl_sync(FULLMASK, inno, b4 + 3);
        float xn = xpred + z0 * in0 + z1 * in1 + z2 * in2 + z3 * in3;
        xreg = xn;
        if (lane < 8) { sX[o] = xn; outX[((long)b * T + t) * 8 + o] = xn; }

        // ==== P_new = Ppred - K Pxy^T + JIT*I (symmetric to fp noise) ====
        const float Ka0 = __shfl_sync(FULLMASK, z0, q);
        const float Ka1 = __shfl_sync(FULLMASK, z1, q);
        const float Ka2 = __shfl_sync(FULLMASK, z2, q);
        const float Ka3 = __shfl_sync(FULLMASK, z3, q);
        const float Kb0 = __shfl_sync(FULLMASK, z0, q + 4);
        const float Kb1 = __shfl_sync(FULLMASK, z1, q + 4);
        const float Kb2 = __shfl_sync(FULLMASK, z2, q + 4);
        const float Kb3 = __shfl_sync(FULLMASK, z3, q + 4);
        float p1 = ppa - (Ka0 * w0 + Ka1 * w1 + Ka2 * w2 + Ka3 * w3) + ((i1 == o) ? JIT : 0.0f);
        float p2 = ppb - (Kb0 * w0 + Kb1 * w1 + Kb2 * w2 + Kb3 * w3) + ((i2 == o) ? JIT : 0.0f);
        sP[i1 * 8 + o] = p1;
        sP[i2 * 8 + o] = p2;
        long bp = ((long)b * T + t) * 64;
        outP[bp + i1 * 8 + o] = p1;
        outP[bp + i2 * 8 + o] = p2;
        __syncwarp();
    }

    // ==== epilogue: q_e[T-1] from final P_pred (root-free pivots) ====
    {
        float a[8];
        #pragma unroll
        for (int c = 0; c < 8; ++c) a[c] = sPp[o * 8 + c];
        float myd = 1.0f;
        #pragma unroll
        for (int k = 0; k < 8; ++k) {
            float dk = __shfl_sync(FULLMASK, a[k], k);
            float isq = rsqrtf(dk);
            float rc = isq * isq;
            myd = (o == k) ? dk : myd;
            float tt = a[k] * rc;
            #pragma unroll
            for (int jj = k + 1; jj < 8; ++jj) {
                float lj = __shfl_sync(FULLMASK, a[k], jj);
                a[jj] -= tt * lj;
            }
        }
        float lg = __logf(myd);
        lg += __shfl_xor_sync(FULLMASK, lg, 1);
        lg += __shfl_xor_sync(FULLMASK, lg, 2);
        lg += __shfl_xor_sync(FULLMASK, lg, 4);
        if (lane == 0) outQ[(long)b * T + (T - 1)] = 0.5f * lg;
    }
}

extern "C" void kernel_launch(void* const* d_in, const int* in_sizes, int n_in,
                              void* d_out, int out_size) {
    const float* X0  = (const float*)d_in[0];
    const float* u   = (const float*)d_in[1];
    const float* yv  = (const float*)d_in[2];
    const float* W1  = (const float*)d_in[3];
    const float* b1  = (const float*)d_in[4];
    const float* W2  = (const float*)d_in[5];
    const float* b2  = (const float*)d_in[6];
    const float* Hm  = (const float*)d_in[7];
    const float* lq  = (const float*)d_in[8];
    const float* lr  = (const float*)d_in[9];
    const float* lp0 = (const float*)d_in[10];

    const int B = in_sizes[0] / 8;                 // 1024
    const int T = in_sizes[1] / (B * 2);           // 256

    float* out  = (float*)d_out;
    float* outX = out;
    float* outP = out + (long)B * T * 8;
    float* outQ = out + (long)B * T * (8 + 64);
    float* outR = outQ + (long)B * T;

    ukf_kernel<<<B, 32>>>(X0, u, yv, W1, b1, W2, b2, Hm, lq, lr, lp0,
                          outX, outP, outQ, outR, T);
}